// round 1
// baseline (speedup 1.0000x reference)
#include <cuda_runtime.h>
#include <math_constants.h>

// MeanMaxPooling: N=4, E=64, L=512, D=256
// in[0]: doc_state    (N, L, D) float32
// in[1]: nodes_mapping(N, E, L) float32 (0/1)
// in[2]: nodes_len    (N, E)    float32
// out  : (N, E, 2*D)  float32  [0:D]=max over masked tokens (incl. 0), [D:2D]=mean

#define N_ 4
#define E_ 64
#define L_ 512
#define D_ 256

__global__ __launch_bounds__(D_, 4)
void meanmax_kernel(const float* __restrict__ doc_state,
                    const float* __restrict__ nodes_mapping,
                    const float* __restrict__ nodes_len,
                    float* __restrict__ out)
{
    // one CTA per (n, e)
    const int ne = blockIdx.x;        // 0..N*E-1
    const int n  = ne >> 6;           // ne / E
    const int e  = ne & 63;           // ne % E
    const int d  = threadIdx.x;       // 0..D-1

    __shared__ int s_idx[L_];
    __shared__ int s_cnt;

    if (threadIdx.x == 0) s_cnt = 0;
    __syncthreads();

    // compact selected token indices (order irrelevant for sum/max within tol)
    const float* mrow = nodes_mapping + ((size_t)n * E_ + e) * L_;
    #pragma unroll
    for (int l = d; l < L_; l += D_) {
        if (mrow[l] != 0.0f) {
            int p = atomicAdd(&s_cnt, 1);
            s_idx[p] = l;
        }
    }
    __syncthreads();

    const int cnt = s_cnt;
    const float* doc = doc_state + (size_t)n * L_ * D_ + d;

    // masked-broadcast max includes 0 whenever any token is unselected
    float acc_max = (cnt < L_) ? 0.0f : -CUDART_INF_F;
    float acc_sum = 0.0f;

    int i = 0;
    // 4-way unrolled independent loads for MLP
    for (; i + 4 <= cnt; i += 4) {
        int l0 = s_idx[i + 0];
        int l1 = s_idx[i + 1];
        int l2 = s_idx[i + 2];
        int l3 = s_idx[i + 3];
        float v0 = doc[(size_t)l0 * D_];
        float v1 = doc[(size_t)l1 * D_];
        float v2 = doc[(size_t)l2 * D_];
        float v3 = doc[(size_t)l3 * D_];
        acc_sum += v0 + v1 + v2 + v3;
        acc_max = fmaxf(acc_max, fmaxf(fmaxf(v0, v1), fmaxf(v2, v3)));
    }
    for (; i < cnt; ++i) {
        float v = doc[(size_t)s_idx[i] * D_];
        acc_sum += v;
        acc_max = fmaxf(acc_max, v);
    }

    float len = nodes_len[(size_t)n * E_ + e];
    float safe_len = (len > 0.0f) ? len : 1.0f;

    float* orow = out + (size_t)ne * (2 * D_);
    orow[d]      = acc_max;
    orow[D_ + d] = acc_sum / safe_len;
}

extern "C" void kernel_launch(void* const* d_in, const int* in_sizes, int n_in,
                              void* d_out, int out_size)
{
    const float* doc_state     = (const float*)d_in[0];
    const float* nodes_mapping = (const float*)d_in[1];
    const float* nodes_len     = (const float*)d_in[2];
    float* out = (float*)d_out;

    dim3 grid(N_ * E_);
    dim3 block(D_);
    meanmax_kernel<<<grid, block>>>(doc_state, nodes_mapping, nodes_len, out);
}

// round 2
// speedup vs baseline: 1.0072x; 1.0072x over previous
#include <cuda_runtime.h>
#include <math_constants.h>

// MeanMaxPooling: N=4, E=64, L=512, D=256
// in[0]: doc_state    (N, L, D) float32
// in[1]: nodes_mapping(N, E, L) float32 (0/1)
// in[2]: nodes_len    (N, E)    float32
// out  : (N, E, 2*D)  float32  [0:D]=max over masked states (incl. 0), [D:2D]=mean

#define N_ 4
#define E_ 64
#define L_ 512
#define D_ 256
#define CH 4            // token chunks per CTA
#define LC (L_ / CH)    // 128 tokens per chunk
#define TX 128          // d-threads; each handles 2 consecutive d (float2)

__global__ __launch_bounds__(TX * CH, 2)
void meanmax_kernel(const float* __restrict__ doc_state,
                    const float* __restrict__ nodes_mapping,
                    const float* __restrict__ nodes_len,
                    float* __restrict__ out)
{
    const int ne  = blockIdx.x;        // (n, e) pair, 0..255
    const int n   = ne >> 6;           // ne / E
    const int tx  = threadIdx.x;       // 0..127 (d pair index)
    const int c   = threadIdx.y;       // 0..3   (token chunk)
    const int tid = c * TX + tx;       // 0..511

    __shared__ int    s_idx[CH][LC];
    __shared__ int    s_cnt[CH];
    __shared__ float2 s_pmax[CH][TX];
    __shared__ float2 s_psum[CH][TX];

    if (tid < CH) s_cnt[tid] = 0;
    __syncthreads();

    // compact selected token indices, partitioned by 128-token chunk
    // (one coalesced 2KB mask-row read: 512 threads, 512 tokens)
    const float* mrow = nodes_mapping + (size_t)ne * L_;
    {
        const int l = tid;
        if (mrow[l] != 0.0f) {
            const int ch = l >> 7;               // l / LC
            const int p  = atomicAdd(&s_cnt[ch], 1);
            s_idx[ch][p] = l;
        }
    }
    __syncthreads();

    const int cnt = s_cnt[c];
    const float2* doc = (const float2*)(doc_state + (size_t)n * L_ * D_) + tx;

    float2 pmax = make_float2(-CUDART_INF_F, -CUDART_INF_F);
    float2 psum = make_float2(0.0f, 0.0f);

    // gather this chunk's ~12.8 tokens in batches of 8 independent loads
    for (int i = 0; i < cnt; i += 8) {
        float2 v[8];
        int    ok[8];
        #pragma unroll
        for (int j = 0; j < 8; ++j) {
            const int k = i + j;
            ok[j] = (k < cnt);
            const int l = s_idx[c][ok[j] ? k : i];   // clamp to a valid slot
            v[j] = doc[(size_t)l * (D_ / 2)];
        }
        #pragma unroll
        for (int j = 0; j < 8; ++j) {
            if (ok[j]) {
                psum.x += v[j].x;
                psum.y += v[j].y;
                pmax.x = fmaxf(pmax.x, v[j].x);
                pmax.y = fmaxf(pmax.y, v[j].y);
            }
        }
    }

    s_pmax[c][tx] = pmax;
    s_psum[c][tx] = psum;
    __syncthreads();

    // chunk 0's threads combine the 4 partials and write out
    if (c == 0) {
        float2 m = s_pmax[0][tx];
        float2 s = s_psum[0][tx];
        #pragma unroll
        for (int q = 1; q < CH; ++q) {
            const float2 mq = s_pmax[q][tx];
            const float2 sq = s_psum[q][tx];
            m.x = fmaxf(m.x, mq.x);
            m.y = fmaxf(m.y, mq.y);
            s.x += sq.x;
            s.y += sq.y;
        }
        const int tot = s_cnt[0] + s_cnt[1] + s_cnt[2] + s_cnt[3];
        if (tot < L_) {                 // mask-broadcast contributes zeros to max
            m.x = fmaxf(m.x, 0.0f);
            m.y = fmaxf(m.y, 0.0f);
        }
        const float len = nodes_len[ne];
        const float sl  = (len > 0.0f) ? len : 1.0f;
        s.x = s.x / sl;
        s.y = s.y / sl;

        float2* orow = (float2*)(out + (size_t)ne * (2 * D_));
        orow[tx]      = m;   // max half
        orow[TX + tx] = s;   // mean half
    }
}

extern "C" void kernel_launch(void* const* d_in, const int* in_sizes, int n_in,
                              void* d_out, int out_size)
{
    const float* doc_state     = (const float*)d_in[0];
    const float* nodes_mapping = (const float*)d_in[1];
    const float* nodes_len     = (const float*)d_in[2];
    float* out = (float*)d_out;

    dim3 grid(N_ * E_);
    dim3 block(TX, CH);
    meanmax_kernel<<<grid, block>>>(doc_state, nodes_mapping, nodes_len, out);
}

// round 3
// speedup vs baseline: 1.2977x; 1.2884x over previous
#include <cuda_runtime.h>
#include <math_constants.h>

// MeanMaxPooling: N=4, E=64, L=512, D=256
// in[0]: doc_state    (N, L, D) float32
// in[1]: nodes_mapping(N, E, L) float32 (0/1)
// in[2]: nodes_len    (N, E)    float32
// out  : (N, E, 2*D)  float32  [0:D]=max over masked states (incl. 0), [D:2D]=mean

#define N_ 4
#define E_ 64
#define L_ 512
#define D_ 256
#define NW 16           // warps per CTA; warp w owns tokens [32w, 32w+32), full D

__global__ __launch_bounds__(NW * 32, 2)
void meanmax_kernel(const float* __restrict__ doc_state,
                    const float* __restrict__ nodes_mapping,
                    const float* __restrict__ nodes_len,
                    float* __restrict__ out)
{
    const int ne   = blockIdx.x;      // (n, e) pair
    const int n    = ne >> 6;         // ne / E
    const int tid  = threadIdx.x;
    const int w    = tid >> 5;        // warp = 32-token chunk
    const int lane = tid & 31;

    __shared__ float4 s_sum[NW][64];  // [warp][d/4]  16 KB
    __shared__ float4 s_max[NW][64];  //              16 KB

    // each warp reads its own 32 mask values -> in-warp bitmask; no barrier needed
    const float mval = nodes_mapping[(size_t)ne * L_ + w * 32 + lane];
    unsigned mb = __ballot_sync(0xffffffffu, mval != 0.0f);

    const float4* doc4 = (const float4*)(doc_state + (size_t)n * L_ * D_);
    const int base = w * 32;

    float4 s0 = make_float4(0.f, 0.f, 0.f, 0.f), s1 = s0;
    float4 m0 = make_float4(-CUDART_INF_F, -CUDART_INF_F, -CUDART_INF_F, -CUDART_INF_F);
    float4 m1 = m0;

    // gather: batches of 4 tokens (8 independent predicated 16B loads)
    while (mb) {
        int  l[4];
        bool ok[4];
        #pragma unroll
        for (int j = 0; j < 4; ++j) {
            ok[j] = (mb != 0u);
            l[j]  = ok[j] ? (__ffs(mb) - 1) : 0;
            mb &= mb - 1u;
        }
        float4 a[4], b[4];
        #pragma unroll
        for (int j = 0; j < 4; ++j) {
            if (ok[j]) {
                const float4* p = doc4 + (size_t)(base + l[j]) * (D_ / 4);
                a[j] = p[lane];        // d = 4*lane .. 4*lane+3
                b[j] = p[32 + lane];   // d = 128+4*lane ..
            }
        }
        #pragma unroll
        for (int j = 0; j < 4; ++j) {
            if (ok[j]) {
                s0.x += a[j].x; s0.y += a[j].y; s0.z += a[j].z; s0.w += a[j].w;
                s1.x += b[j].x; s1.y += b[j].y; s1.z += b[j].z; s1.w += b[j].w;
                m0.x = fmaxf(m0.x, a[j].x); m0.y = fmaxf(m0.y, a[j].y);
                m0.z = fmaxf(m0.z, a[j].z); m0.w = fmaxf(m0.w, a[j].w);
                m1.x = fmaxf(m1.x, b[j].x); m1.y = fmaxf(m1.y, b[j].y);
                m1.z = fmaxf(m1.z, b[j].z); m1.w = fmaxf(m1.w, b[j].w);
            }
        }
    }

    s_sum[w][lane]      = s0;
    s_sum[w][32 + lane] = s1;
    s_max[w][lane]      = m0;
    s_max[w][32 + lane] = m1;
    __syncthreads();

    // merge 16 partials; warps 0-1 -> max half, warps 2-3 -> sum half (no divergence)
    if (tid < 128) {
        const bool is_max = (tid < 64);
        const int  j = is_max ? tid : (tid - 64);   // float4 slot, 0..63

        float4 r = is_max ? s_max[0][j] : s_sum[0][j];
        #pragma unroll
        for (int q = 1; q < NW; ++q) {
            const float4 p = is_max ? s_max[q][j] : s_sum[q][j];
            if (is_max) {
                r.x = fmaxf(r.x, p.x); r.y = fmaxf(r.y, p.y);
                r.z = fmaxf(r.z, p.z); r.w = fmaxf(r.w, p.w);
            } else {
                r.x += p.x; r.y += p.y; r.z += p.z; r.w += p.w;
            }
        }

        const float len = nodes_len[ne];
        float4* orow = (float4*)(out + (size_t)ne * (2 * D_));
        if (is_max) {
            if (len < (float)L_) {      // any masked-out token => 0 participates in max
                r.x = fmaxf(r.x, 0.f); r.y = fmaxf(r.y, 0.f);
                r.z = fmaxf(r.z, 0.f); r.w = fmaxf(r.w, 0.f);
            }
            orow[j] = r;
        } else {
            const float inv = 1.0f / ((len > 0.f) ? len : 1.f);
            r.x *= inv; r.y *= inv; r.z *= inv; r.w *= inv;
            orow[(D_ / 4) + j] = r;
        }
    }
}

extern "C" void kernel_launch(void* const* d_in, const int* in_sizes, int n_in,
                              void* d_out, int out_size)
{
    const float* doc_state     = (const float*)d_in[0];
    const float* nodes_mapping = (const float*)d_in[1];
    const float* nodes_len     = (const float*)d_in[2];
    float* out = (float*)d_out;

    meanmax_kernel<<<N_ * E_, NW * 32>>>(doc_state, nodes_mapping, nodes_len, out);
}